// round 16
// baseline (speedup 1.0000x reference)
#include <cuda_runtime.h>
#include <cuda_fp16.h>
#include <cstdint>
#include <cstring>

// ---------------------------------------------------------------------------
// LightOnOcrPatchMerger: 2x2 patch merge (unfold) + Linear(4096 -> 1024).
// R16 = R15 resubmission (GB300 container infra failure, no measurement).
// Fuse the A gather + fp32->fp16 convert INTO the GEMM loader (pack_A
// kernel deleted; saves ~55us + a 138MB round-trip). B stays packed fp16 via
// pack_W (8us). GEMM is at the legacy-HMMA issue ceiling (~15cyc/mma/SMSP,
// measured invariant across R1/R6/R9 schedules), so loads hide under compute.
// Key: with BK=32, quadrant q = kt>>5 is constant per stage -> each A-tile row
// reads ONE contiguous 32-float span of one feats row (gather base computed
// once per thread).  (tcgen05 unavailable: harness PTX target lacks 'a'.)
// ---------------------------------------------------------------------------

#define M_TOTAL 16860
#define N_TOTAL 1024
#define K_TOTAL 4096
#define HID     1024

__constant__ int c_moff[8] = {0, 3025, 5225, 6985, 8245, 11161, 13361, 14385};
__constant__ int c_foff[8] = {0, 12100, 20900, 27940, 32980, 44644, 53444, 57540};
__constant__ int c_wp[8]   = {110, 110, 64, 90, 108, 80, 64, 110};

__device__ __align__(16) __half g_W[(size_t)N_TOTAL * K_TOTAL];  // 8 MB

// ---------------------------------------------------------------------------
__global__ void pack_W_kernel(const float* __restrict__ W) {
    int idx = blockIdx.x * blockDim.x + threadIdx.x;
    int o = idx >> 12;
    int c = idx & 4095;
    int q = c >> 10;
    int d = c & 1023;
    g_W[idx] = __float2half(W[(size_t)o * 4096 + d * 4 + q]);
}

// ---------------------------------------------------------------------------
// GEMM: 128x128 CTA, 8 warps (4 M x 2 N), warp tile 32x64, BK=32.
// A: 3-buffer smem pipeline fed by LDG.fp32 + cvt + STS (fused gather).
// B: 4-stage cp.async pipeline from packed g_W.
// ---------------------------------------------------------------------------
#define BM 128
#define BN 128
#define BK 32
#define ABUF 3
#define BSTAGE 4
#define SPAD 8
#define SSTRIDE (BK + SPAD)            // 40 halves = 80B row stride
#define KT (K_TOTAL / BK)              // 128 iterations

#define TILE_H (BM * SSTRIDE)          // 5120 halves per buffer
#define SMEM_BYTES ((ABUF + BSTAGE) * TILE_H * 2)   // 71680 B

__device__ __forceinline__ uint32_t h2_bits(__half2 h) {
    uint32_t u;
    memcpy(&u, &h, 4);
    return u;
}

__device__ __forceinline__ void cp_async16(void* smem, const void* gmem) {
    uint32_t s = (uint32_t)__cvta_generic_to_shared(smem);
    asm volatile("cp.async.cg.shared.global [%0], [%1], 16;\n"
                 :: "r"(s), "l"(gmem));
}

__device__ __forceinline__ void ldmatrix_x4(uint32_t& r0, uint32_t& r1,
                                            uint32_t& r2, uint32_t& r3,
                                            const void* ptr) {
    uint32_t addr = (uint32_t)__cvta_generic_to_shared(ptr);
    asm volatile("ldmatrix.sync.aligned.m8n8.x4.shared.b16 {%0,%1,%2,%3}, [%4];"
                 : "=r"(r0), "=r"(r1), "=r"(r2), "=r"(r3)
                 : "r"(addr));
}

__device__ __forceinline__ void mma_16816(float* c, const uint32_t* a,
                                          uint32_t b0, uint32_t b1) {
    asm volatile(
        "mma.sync.aligned.m16n8k16.row.col.f32.f16.f16.f32 "
        "{%0,%1,%2,%3}, {%4,%5,%6,%7}, {%8,%9}, {%0,%1,%2,%3};\n"
        : "+f"(c[0]), "+f"(c[1]), "+f"(c[2]), "+f"(c[3])
        : "r"(a[0]), "r"(a[1]), "r"(a[2]), "r"(a[3]), "r"(b0), "r"(b1));
}

__global__ __launch_bounds__(256, 2) void gemm_fused_kernel(
        const float* __restrict__ feats, float* __restrict__ out) {
    extern __shared__ __align__(16) __half smem[];
    __half* sAbase = smem;                       // 3 x TILE_H
    __half* sBbase = smem + ABUF * TILE_H;       // 4 x TILE_H

    const int tid  = threadIdx.x;
    const int warp = tid >> 5;
    const int lane = tid & 31;
    const int wm = warp & 3;   // 0..3 -> 32-row slice
    const int wn = warp >> 2;  // 0..1 -> 64-col slice

    const int mbase = blockIdx.y * BM;
    const int nbase = blockIdx.x * BN;

    // ---- per-thread A-gather base (computed once): row = tid>>1
    const int arow  = tid >> 1;
    const int alane = tid & 1;              // which 16-half half of the 32-col stage
    const int tr    = mbase + arow;
    const bool avalid = (tr < M_TOTAL);
    int fbase = 0, awp = 0;
    {
        int t = avalid ? tr : 0;
        int img = 0;
#pragma unroll
        for (int i = 1; i < 8; ++i)
            if (t >= c_moff[i]) img = i;
        int tl = t - c_moff[img];
        awp = c_wp[img];
        int hw = awp >> 1;
        int bi = tl / hw;
        int bj = tl - bi * hw;
        fbase = c_foff[img] + (2 * bi) * awp + 2 * bj;
    }

    // A loader: kt -> 8 packed half2 regs (16 halves)
    uint32_t av[8];
    auto loadA = [&](int kt) {
        int q  = kt >> 5;
        int d0 = ((kt & 31) << 5) + (alane << 4);
        int r  = fbase + (q >> 1) * awp + (q & 1);
        if (avalid) {
            const float4* p = reinterpret_cast<const float4*>(
                feats + (size_t)r * HID + d0);
#pragma unroll
            for (int i = 0; i < 4; ++i) {
                float4 f = p[i];
                av[2 * i]     = h2_bits(__floats2half2_rn(f.x, f.y));
                av[2 * i + 1] = h2_bits(__floats2half2_rn(f.z, f.w));
            }
        } else {
#pragma unroll
            for (int i = 0; i < 8; ++i) av[i] = 0u;
        }
    };
    auto stsA = [&](int kt) {
        __half* dst = sAbase + (kt % ABUF) * TILE_H + arow * SSTRIDE + (alane << 4);
        uint4* d4 = reinterpret_cast<uint4*>(dst);
        d4[0] = make_uint4(av[0], av[1], av[2], av[3]);
        d4[1] = make_uint4(av[4], av[5], av[6], av[7]);
    };

    // B loader: 512 x 16B chunks, 256 threads -> 2 each
    auto loadB = [&](int kt) {
        const int kbase = kt * BK;
        __half* sB = sBbase + (kt % BSTAGE) * TILE_H;
#pragma unroll
        for (int it = 0; it < 2; ++it) {
            int cid = tid + it * 256;
            int row = cid >> 2;
            int c16 = cid & 3;
            const __half* src = g_W + (size_t)(nbase + row) * K_TOTAL + kbase + c16 * 8;
            cp_async16(&sB[row * SSTRIDE + c16 * 8], src);
        }
    };

    float acc[2][8][4];
#pragma unroll
    for (int i = 0; i < 2; ++i)
#pragma unroll
        for (int j = 0; j < 8; ++j)
#pragma unroll
            for (int k = 0; k < 4; ++k) acc[i][j][k] = 0.f;

    // ---- prologue
    loadA(0); stsA(0);
    loadA(1);
#pragma unroll
    for (int s = 0; s < BSTAGE - 1; ++s) {
        loadB(s);
        asm volatile("cp.async.commit_group;\n");
    }
    __syncthreads();

    const int lr = lane & 15;
    const int lc = (lane >> 4) << 3;

    for (int kt = 0; kt < KT; ++kt) {
        // stage A(kt+1) into smem (regs loaded last iter); fetch A(kt+2)
        if (kt + 1 < KT) stsA(kt + 1);
        if (kt + 2 < KT) loadA(kt + 2);
        // B: issue stage kt+3, keep group count uniform
        if (kt + BSTAGE - 1 < KT) loadB(kt + BSTAGE - 1);
        asm volatile("cp.async.commit_group;\n");
        asm volatile("cp.async.wait_group %0;\n" :: "n"(BSTAGE - 2));
        __syncthreads();   // A(kt) visible (written iter kt-1) + B(kt) ready

        const __half* sA = sAbase + (kt % ABUF) * TILE_H;
        const __half* sB = sBbase + (kt % BSTAGE) * TILE_H;

#pragma unroll
        for (int ks = 0; ks < 2; ++ks) {
            uint32_t a[2][4];
            uint32_t b[4][4];
#pragma unroll
            for (int mt = 0; mt < 2; ++mt)
                ldmatrix_x4(a[mt][0], a[mt][1], a[mt][2], a[mt][3],
                            &sA[(wm * 32 + mt * 16 + lr) * SSTRIDE + ks * 16 + lc]);
#pragma unroll
            for (int nt2 = 0; nt2 < 4; ++nt2)
                ldmatrix_x4(b[nt2][0], b[nt2][1], b[nt2][2], b[nt2][3],
                            &sB[(wn * 64 + nt2 * 16 + lr) * SSTRIDE + ks * 16 + lc]);
#pragma unroll
            for (int mt = 0; mt < 2; ++mt)
#pragma unroll
                for (int nt2 = 0; nt2 < 4; ++nt2) {
                    mma_16816(acc[mt][nt2 * 2 + 0], a[mt], b[nt2][0], b[nt2][2]);
                    mma_16816(acc[mt][nt2 * 2 + 1], a[mt], b[nt2][1], b[nt2][3]);
                }
        }
        __syncthreads();   // all reads of this A/B slot done before rewrite
    }

    // ---- epilogue: direct fp32 stores (float2 per fragment half)
#pragma unroll
    for (int mt = 0; mt < 2; ++mt) {
#pragma unroll
        for (int nt = 0; nt < 8; ++nt) {
            int r0 = mbase + wm * 32 + mt * 16 + (lane >> 2);
            int col = nbase + wn * 64 + nt * 8 + ((lane & 3) << 1);
            if (r0 < M_TOTAL) {
                float2 v = {acc[mt][nt][0], acc[mt][nt][1]};
                *reinterpret_cast<float2*>(&out[(size_t)r0 * N_TOTAL + col]) = v;
            }
            int r1 = r0 + 8;
            if (r1 < M_TOTAL) {
                float2 v = {acc[mt][nt][2], acc[mt][nt][3]};
                *reinterpret_cast<float2*>(&out[(size_t)r1 * N_TOTAL + col]) = v;
            }
        }
    }
}

// ---------------------------------------------------------------------------
extern "C" void kernel_launch(void* const* d_in, const int* in_sizes, int n_in,
                              void* d_out, int out_size) {
    const float* feats = (const float*)d_in[0];   // [67440, 1024] fp32
    const float* W     = (const float*)d_in[1];   // [1024, 4096]  fp32
    float* out = (float*)d_out;                   // [16860, 1024] fp32

    pack_W_kernel<<<(N_TOTAL * K_TOTAL) / 256, 256>>>(W);

    cudaFuncSetAttribute(gemm_fused_kernel,
                         cudaFuncAttributeMaxDynamicSharedMemorySize, SMEM_BYTES);
    dim3 grid(N_TOTAL / BN, (M_TOTAL + BM - 1) / BM);  // N fastest -> A L2 reuse
    gemm_fused_kernel<<<grid, 256, SMEM_BYTES>>>(feats, out);
}

// round 17
// speedup vs baseline: 1.4657x; 1.4657x over previous
#include <cuda_runtime.h>
#include <cuda_fp16.h>
#include <cstdint>

// ---------------------------------------------------------------------------
// LightOnOcrPatchMerger: 2x2 patch merge (unfold) + Linear(4096 -> 1024).
// R17: revert to split pack_A/pack_W (fusion measured BAD: 774us, R16) and
// attack the GEMM's tensor-pipe utilization (measured 30-48% vs ~230us floor):
//   - 3-stage cp.async pipeline (was 2): wait_group 1 gains a stage of slack.
//   - fragment batching: all 24 ldmatrix (both ks) issued before any mma, so
//     ks=1 ldsm latency hides under ks=0 mmas.
// Same proven 128x128 / 8-warp / 32x64-warptile / 2-CTA-per-SM R1 skeleton.
// (tcgen05 unavailable: harness PTX target lacks the 'a' suffix.)
// ---------------------------------------------------------------------------

#define M_TOTAL 16860
#define N_TOTAL 1024
#define K_TOTAL 4096
#define HID     1024

__constant__ int c_moff[8] = {0, 3025, 5225, 6985, 8245, 11161, 13361, 14385};
__constant__ int c_foff[8] = {0, 12100, 20900, 27940, 32980, 44644, 53444, 57540};
__constant__ int c_wp[8]   = {110, 110, 64, 90, 108, 80, 64, 110};

__device__ __align__(16) __half g_A[(size_t)M_TOTAL * K_TOTAL];  // 138 MB
__device__ __align__(16) __half g_W[(size_t)N_TOTAL * K_TOTAL];  // 8 MB

// ---------------------------------------------------------------------------
__global__ void pack_A_kernel(const float* __restrict__ feats) {
    int t = blockIdx.x;
    int img = 0;
#pragma unroll
    for (int i = 1; i < 8; ++i)
        if (t >= c_moff[i]) img = i;
    int tl = t - c_moff[img];
    int wp = c_wp[img];
    int hw = wp >> 1;
    int bi = tl / hw;
    int bj = tl - bi * hw;
    int base = c_foff[img] + (2 * bi) * wp + 2 * bj;

    int tid = threadIdx.x;
#pragma unroll
    for (int q = 0; q < 4; ++q) {
        int r = base + (q >> 1) * wp + (q & 1);
        const float4* src = reinterpret_cast<const float4*>(feats + (size_t)r * HID);
        float4 v = src[tid];
        __half2 h0 = __floats2half2_rn(v.x, v.y);
        __half2 h1 = __floats2half2_rn(v.z, v.w);
        __half2* dst = reinterpret_cast<__half2*>(g_A + (size_t)t * K_TOTAL + q * HID) + tid * 2;
        dst[0] = h0;
        dst[1] = h1;
    }
}

__global__ void pack_W_kernel(const float* __restrict__ W) {
    int idx = blockIdx.x * blockDim.x + threadIdx.x;
    int o = idx >> 12;
    int c = idx & 4095;
    int q = c >> 10;
    int d = c & 1023;
    g_W[idx] = __float2half(W[(size_t)o * 4096 + d * 4 + q]);
}

// ---------------------------------------------------------------------------
// GEMM: 128x128 CTA, 8 warps (4 M x 2 N), warp tile 32x64, BK=32, 3 stages.
// ---------------------------------------------------------------------------
#define BM 128
#define BN 128
#define BK 32
#define NSTAGE 3
#define SPAD 8
#define SSTRIDE (BK + SPAD)            // 40 halves = 80B row stride
#define KT (K_TOTAL / BK)              // 128 iterations

#define A_STAGE_H (BM * SSTRIDE)       // 5120 halves
#define B_STAGE_H (BN * SSTRIDE)       // 5120 halves
#define STAGE_H   (A_STAGE_H + B_STAGE_H)
#define SMEM_BYTES (NSTAGE * STAGE_H * 2)   // 61440 B -> 2 CTAs/SM

__device__ __forceinline__ void cp_async16(void* smem, const void* gmem, bool pred) {
    uint32_t s = (uint32_t)__cvta_generic_to_shared(smem);
    int sz = pred ? 16 : 0;
    asm volatile("cp.async.cg.shared.global [%0], [%1], 16, %2;\n"
                 :: "r"(s), "l"(gmem), "r"(sz));
}

__device__ __forceinline__ void ldmatrix_x4(uint32_t& r0, uint32_t& r1,
                                            uint32_t& r2, uint32_t& r3,
                                            const void* ptr) {
    uint32_t addr = (uint32_t)__cvta_generic_to_shared(ptr);
    asm volatile("ldmatrix.sync.aligned.m8n8.x4.shared.b16 {%0,%1,%2,%3}, [%4];"
                 : "=r"(r0), "=r"(r1), "=r"(r2), "=r"(r3)
                 : "r"(addr));
}

__device__ __forceinline__ void mma_16816(float* c, const uint32_t* a,
                                          uint32_t b0, uint32_t b1) {
    asm volatile(
        "mma.sync.aligned.m16n8k16.row.col.f32.f16.f16.f32 "
        "{%0,%1,%2,%3}, {%4,%5,%6,%7}, {%8,%9}, {%0,%1,%2,%3};\n"
        : "+f"(c[0]), "+f"(c[1]), "+f"(c[2]), "+f"(c[3])
        : "r"(a[0]), "r"(a[1]), "r"(a[2]), "r"(a[3]), "r"(b0), "r"(b1));
}

__global__ __launch_bounds__(256, 2) void gemm_kernel(float* __restrict__ out) {
    extern __shared__ __align__(16) __half smem[];

    const int tid  = threadIdx.x;
    const int warp = tid >> 5;
    const int lane = tid & 31;
    const int wm = warp & 3;   // 0..3 -> 32-row slice
    const int wn = warp >> 2;  // 0..1 -> 64-col slice

    const int mbase = blockIdx.y * BM;
    const int nbase = blockIdx.x * BN;

    float acc[2][8][4];
#pragma unroll
    for (int i = 0; i < 2; ++i)
#pragma unroll
        for (int j = 0; j < 8; ++j)
#pragma unroll
            for (int k = 0; k < 4; ++k) acc[i][j][k] = 0.f;

    // ---- stage loader: A 128x32 + B 128x32 = 1024 x 16B chunks, 256 threads
    auto load_stage = [&](int s, int kt) {
        const int kbase = kt * BK;
        __half* sA = smem + s * STAGE_H;
        __half* sB = sA + A_STAGE_H;
#pragma unroll
        for (int it = 0; it < 2; ++it) {
            int cid = tid + it * 256;
            int row = cid >> 2;
            int c16 = cid & 3;
            int gr = mbase + row;
            const __half* src = g_A + (size_t)gr * K_TOTAL + kbase + c16 * 8;
            cp_async16(&sA[row * SSTRIDE + c16 * 8], src, gr < M_TOTAL);
        }
#pragma unroll
        for (int it = 0; it < 2; ++it) {
            int cid = tid + it * 256;
            int row = cid >> 2;
            int c16 = cid & 3;
            const __half* src = g_W + (size_t)(nbase + row) * K_TOTAL + kbase + c16 * 8;
            cp_async16(&sB[row * SSTRIDE + c16 * 8], src, true);
        }
    };

    // ---- prologue: stages 0..1
#pragma unroll
    for (int s = 0; s < NSTAGE - 1; ++s) {
        load_stage(s, s);
        asm volatile("cp.async.commit_group;\n");
    }

    const int lr = lane & 15;
    const int lc = (lane >> 4) << 3;

    for (int kt = 0; kt < KT; ++kt) {
        asm volatile("cp.async.wait_group 1;\n");
        __syncthreads();   // stage kt ready; all warps done reading stage kt-1

        // issue loads for stage kt+2 (slot == (kt-1)%3, just freed)
        if (kt + 2 < KT)
            load_stage((kt + 2) % NSTAGE, kt + 2);
        asm volatile("cp.async.commit_group;\n");

        const __half* sA = smem + (kt % NSTAGE) * STAGE_H;
        const __half* sB = sA + A_STAGE_H;

        // ---- batch ALL ldmatrix (both ks) before any mma: ks=1 ldsm latency
        //      hides under ks=0's 32 mmas.
        uint32_t a[2][2][4];   // [ks][mt][reg]
        uint32_t b[2][4][4];   // [ks][nt2][reg]
#pragma unroll
        for (int ks = 0; ks < 2; ++ks) {
#pragma unroll
            for (int mt = 0; mt < 2; ++mt)
                ldmatrix_x4(a[ks][mt][0], a[ks][mt][1], a[ks][mt][2], a[ks][mt][3],
                            &sA[(wm * 32 + mt * 16 + lr) * SSTRIDE + ks * 16 + lc]);
#pragma unroll
            for (int nt2 = 0; nt2 < 4; ++nt2)
                ldmatrix_x4(b[ks][nt2][0], b[ks][nt2][1], b[ks][nt2][2], b[ks][nt2][3],
                            &sB[(wn * 64 + nt2 * 16 + lr) * SSTRIDE + ks * 16 + lc]);
        }
#pragma unroll
        for (int ks = 0; ks < 2; ++ks)
#pragma unroll
            for (int mt = 0; mt < 2; ++mt)
#pragma unroll
                for (int nt2 = 0; nt2 < 4; ++nt2) {
                    mma_16816(acc[mt][nt2 * 2 + 0], a[ks][mt], b[ks][nt2][0], b[ks][nt2][2]);
                    mma_16816(acc[mt][nt2 * 2 + 1], a[ks][mt], b[ks][nt2][1], b[ks][nt2][3]);
                }
    }

    // ---- epilogue: direct fp32 stores (float2 per fragment half)
#pragma unroll
    for (int mt = 0; mt < 2; ++mt) {
#pragma unroll
        for (int nt = 0; nt < 8; ++nt) {
            int r0 = mbase + wm * 32 + mt * 16 + (lane >> 2);
            int col = nbase + wn * 64 + nt * 8 + ((lane & 3) << 1);
            if (r0 < M_TOTAL) {
                float2 v = {acc[mt][nt][0], acc[mt][nt][1]};
                *reinterpret_cast<float2*>(&out[(size_t)r0 * N_TOTAL + col]) = v;
            }
            int r1 = r0 + 8;
            if (r1 < M_TOTAL) {
                float2 v = {acc[mt][nt][2], acc[mt][nt][3]};
                *reinterpret_cast<float2*>(&out[(size_t)r1 * N_TOTAL + col]) = v;
            }
        }
    }
}

// ---------------------------------------------------------------------------
extern "C" void kernel_launch(void* const* d_in, const int* in_sizes, int n_in,
                              void* d_out, int out_size) {
    const float* feats = (const float*)d_in[0];   // [67440, 1024] fp32
    const float* W     = (const float*)d_in[1];   // [1024, 4096]  fp32
    float* out = (float*)d_out;                   // [16860, 1024] fp32

    pack_A_kernel<<<M_TOTAL, 256>>>(feats);
    pack_W_kernel<<<(N_TOTAL * K_TOTAL) / 256, 256>>>(W);

    cudaFuncSetAttribute(gemm_kernel,
                         cudaFuncAttributeMaxDynamicSharedMemorySize, SMEM_BYTES);
    dim3 grid(N_TOTAL / BN, (M_TOTAL + BM - 1) / BM);  // N fastest -> A L2 reuse
    gemm_kernel<<<grid, 256, SMEM_BYTES>>>(out);
}